// round 1
// baseline (speedup 1.0000x reference)
#include <cuda_runtime.h>
#include <cuda_bf16.h>

// RNN scan: h_{t+1} = tanh(x_t*W_ih + b_ih + h_t @ W_hh^T + b_hh), HID=4.
// Outputs: y_last = h_S @ fc_W^T + fc_b  (B floats), then hn = h_S (B*4 floats).
//
// State kept as r_k = 1/(1 + 2^{a_k}) so that h_k = 1 - 2 r_k, with
//   a_j = bias_j + (c*wih_j)*x + sum_k V_jk * r_k,
//   c = 2*log2(e), V_jk = -2*c*W_hh[j][k],
//   bias_j = c*(b_ih_j + b_hh_j + sum_k W_hh[j][k]).
// tanh is computed via ex2.approx + rcp.approx (rel err ~1e-7, safe vs tanh.approx).

#define HID 4
#define PD  16   // prefetch ring depth: PD * ~80cyc/step >> 577cyc DRAM latency

__device__ __forceinline__ float fast_ex2(float x) {
    float y; asm("ex2.approx.f32 %0, %1;" : "=f"(y) : "f"(x)); return y;
}
__device__ __forceinline__ float fast_rcp(float x) {
    float y; asm("rcp.approx.f32 %0, %1;" : "=f"(y) : "f"(x)); return y;
}

__global__ __launch_bounds__(64, 1)
void rnn_scan_kernel(const float* __restrict__ x,
                     const float* __restrict__ h0,
                     const float* __restrict__ W_ih,
                     const float* __restrict__ b_ih,
                     const float* __restrict__ W_hh,
                     const float* __restrict__ b_hh,
                     const float* __restrict__ fc_W,
                     const float* __restrict__ fc_b,
                     float* __restrict__ out,
                     int S, int B)
{
    const int b = blockIdx.x * blockDim.x + threadIdx.x;
    if (b >= B) return;

    const float c = 2.8853900817779268f;  // 2*log2(e)

    // Precompute folded constants (uniform across threads; lives in registers).
    float V[HID][HID], bias[HID], wv[HID];
    #pragma unroll
    for (int j = 0; j < HID; ++j) {
        float rowsum = 0.0f;
        #pragma unroll
        for (int k = 0; k < HID; ++k) {
            float w = __ldg(&W_hh[j * HID + k]);
            V[j][k] = -2.0f * c * w;
            rowsum += w;
        }
        bias[j] = c * (__ldg(&b_ih[j]) + __ldg(&b_hh[j]) + rowsum);
        wv[j]   = c * __ldg(&W_ih[j]);
    }

    // State: r_k = (1 - h_k) / 2
    float r[HID];
    #pragma unroll
    for (int k = 0; k < HID; ++k)
        r[k] = 0.5f * (1.0f - h0[(size_t)b * HID + k]);

    // Software prefetch ring over the time dimension (stride B, coalesced).
    const float* xp = x + b;
    float buf[PD];
    #pragma unroll
    for (int i = 0; i < PD; ++i)
        buf[i] = __ldcs(xp + (size_t)i * B);

    for (int t = 0; t < S; t += PD) {
        #pragma unroll
        for (int i = 0; i < PD; ++i) {
            const float xv = buf[i];
            const int tn = t + i + PD;
            buf[i] = (tn < S) ? __ldcs(xp + (size_t)tn * B) : 0.0f;

            float nr[HID];
            #pragma unroll
            for (int j = 0; j < HID; ++j) {
                // a = bias + wv*x + V[j].r   (balanced tree: ~12 cyc from r)
                float abase = fmaf(xv, wv[j], bias[j]);           // indep of r
                float t01 = fmaf(V[j][1], r[1], fmaf(V[j][0], r[0], abase));
                float t23 = fmaf(V[j][3], r[3], V[j][2] * r[2]);
                float a   = t01 + t23;
                float e   = fast_ex2(a);                          // 2^a
                nr[j]     = fast_rcp(e + 1.0f);                   // 1/(1+2^a)
            }
            #pragma unroll
            for (int j = 0; j < HID; ++j) r[j] = nr[j];
        }
    }

    // Epilogue: h = 1 - 2r; y = fc(h); write y_last then hn.
    float y = __ldg(&fc_b[0]);
    float h[HID];
    #pragma unroll
    for (int k = 0; k < HID; ++k) {
        h[k] = fmaf(-2.0f, r[k], 1.0f);
        y = fmaf(__ldg(&fc_W[k]), h[k], y);
    }
    out[b] = y;                                   // y_last: (B,1)
    float* hn = out + B;                          // hn: (1,B,HID)
    #pragma unroll
    for (int k = 0; k < HID; ++k)
        hn[(size_t)b * HID + k] = h[k];
}

extern "C" void kernel_launch(void* const* d_in, const int* in_sizes, int n_in,
                              void* d_out, int out_size)
{
    const float* x    = (const float*)d_in[0];
    const float* h0   = (const float*)d_in[1];
    const float* W_ih = (const float*)d_in[2];
    const float* b_ih = (const float*)d_in[3];
    const float* W_hh = (const float*)d_in[4];
    const float* b_hh = (const float*)d_in[5];
    const float* fc_W = (const float*)d_in[6];
    const float* fc_b = (const float*)d_in[7];
    float* out = (float*)d_out;

    const int B = in_sizes[1] / HID;      // h0 has B*HID elements
    const int S = in_sizes[0] / B;        // x has S*B elements

    const int threads = 64;               // 2 warps/block -> <=1 warp per SMSP chip-wide
    const int blocks = (B + threads - 1) / threads;
    rnn_scan_kernel<<<blocks, threads>>>(x, h0, W_ih, b_ih, W_hh, b_hh,
                                         fc_W, fc_b, out, S, B);
}

// round 2
// speedup vs baseline: 1.1041x; 1.1041x over previous
#include <cuda_runtime.h>
#include <cuda_bf16.h>

// RNN scan: h_{t+1} = tanh(x_t*W_ih + b_ih + h_t @ W_hh^T + b_hh), HID=4.
// Outputs: y_last = h_S @ fc_W^T + fc_b  (B floats), then hn = h_S (B*4 floats).
//
// State kept as r_k = 1/(1 + 2^{a_k}) so h_k = 1 - 2 r_k, with
//   a_j = bias_j + (c*wih_j)*x + sum_k V_jk * r_k,
//   c = 2*log2(e), V_jk = -2*c*W_hh[j][k],
//   bias_j = c*(b_ih_j + b_hh_j + sum_k W_hh[j][k]).
// tanh via ex2.approx + rcp.approx (rel err ~1e-7 per step; measured
// amplification over 4096 steps is ~2.5x -> final ~4e-7, far under 1e-3).
//
// Perf model (B300): per warp-step MUFU pipe = 8 x rt8 = 64 cyc (binding),
// fma pipe ~50 cyc, dependency chain ~48 cyc. This version removes the
// R1 overheads: no nr->r register copies, no predicated/ternary prefetch
// (wrapped always-valid index; wrapped loads are never consumed), serial
// dot accumulation.

#define HID 4
#define PD  16   // prefetch depth: PD * ~80cyc/step covers ~600-1000cyc DRAM lat

__device__ __forceinline__ float fast_ex2(float x) {
    float y; asm("ex2.approx.f32 %0, %1;" : "=f"(y) : "f"(x)); return y;
}
__device__ __forceinline__ float fast_rcp(float x) {
    float y; asm("rcp.approx.f32 %0, %1;" : "=f"(y) : "f"(x)); return y;
}

__global__ __launch_bounds__(64, 1)
void rnn_scan_kernel(const float* __restrict__ x,
                     const float* __restrict__ h0,
                     const float* __restrict__ W_ih,
                     const float* __restrict__ b_ih,
                     const float* __restrict__ W_hh,
                     const float* __restrict__ b_hh,
                     const float* __restrict__ fc_W,
                     const float* __restrict__ fc_b,
                     float* __restrict__ out,
                     int S, int B)
{
    const int b = blockIdx.x * blockDim.x + threadIdx.x;
    if (b >= B) return;

    const float c = 2.8853900817779268f;  // 2*log2(e)

    // Folded constants (uniform across threads; registers).
    float V[HID][HID], bias[HID], wv[HID];
    #pragma unroll
    for (int j = 0; j < HID; ++j) {
        float rowsum = 0.0f;
        #pragma unroll
        for (int k = 0; k < HID; ++k) {
            float w = __ldg(&W_hh[j * HID + k]);
            V[j][k] = -2.0f * c * w;
            rowsum += w;
        }
        bias[j] = c * (__ldg(&b_ih[j]) + __ldg(&b_hh[j]) + rowsum);
        wv[j]   = c * __ldg(&W_ih[j]);
    }

    // State: r_k = (1 - h_k) / 2
    float r[HID];
    #pragma unroll
    for (int k = 0; k < HID; ++k)
        r[k] = 0.5f * (1.0f - h0[(size_t)b * HID + k]);

    // Prefetch ring over time (stride B floats, coalesced across the warp).
    const float* xp = x + b;
    float buf[PD];
    #pragma unroll
    for (int i = 0; i < PD; ++i)
        buf[i] = __ldcs(xp + (size_t)i * B);

    for (int t = 0; t < S; t += PD) {
        #pragma unroll
        for (int i = 0; i < PD; ++i) {
            const float xv = buf[i];
            // Always-valid prefetch index: entries for tn >= S are never
            // consumed as xv (loop ends at S), so redirect them to 0.
            int tn = t + i + PD;
            tn = (tn < S) ? tn : 0;
            buf[i] = __ldcs(xp + (size_t)tn * B);

            // Phase 1: all four dots read the old r (no copies needed).
            float a[HID];
            #pragma unroll
            for (int j = 0; j < HID; ++j) {
                float aj = fmaf(xv, wv[j], bias[j]);       // indep of r
                aj = fmaf(V[j][0], r[0], aj);
                aj = fmaf(V[j][1], r[1], aj);
                aj = fmaf(V[j][2], r[2], aj);
                aj = fmaf(V[j][3], r[3], aj);
                a[j] = aj;
            }
            // Phase 2: MUFU phase writes r in place.
            float e[HID];
            #pragma unroll
            for (int j = 0; j < HID; ++j) e[j] = fast_ex2(a[j]);
            #pragma unroll
            for (int j = 0; j < HID; ++j) r[j] = fast_rcp(e[j] + 1.0f);
        }
    }

    // Epilogue: h = 1 - 2r; y = fc(h); write y_last then hn.
    float y = __ldg(&fc_b[0]);
    float h[HID];
    #pragma unroll
    for (int k = 0; k < HID; ++k) {
        h[k] = fmaf(-2.0f, r[k], 1.0f);
        y = fmaf(__ldg(&fc_W[k]), h[k], y);
    }
    out[b] = y;                                   // y_last: (B,1)
    float* hn = out + B;                          // hn: (1,B,HID)
    #pragma unroll
    for (int k = 0; k < HID; ++k)
        hn[(size_t)b * HID + k] = h[k];
}

extern "C" void kernel_launch(void* const* d_in, const int* in_sizes, int n_in,
                              void* d_out, int out_size)
{
    const float* x    = (const float*)d_in[0];
    const float* h0   = (const float*)d_in[1];
    const float* W_ih = (const float*)d_in[2];
    const float* b_ih = (const float*)d_in[3];
    const float* W_hh = (const float*)d_in[4];
    const float* b_hh = (const float*)d_in[5];
    const float* fc_W = (const float*)d_in[6];
    const float* fc_b = (const float*)d_in[7];
    float* out = (float*)d_out;

    const int B = in_sizes[1] / HID;      // h0 has B*HID elements
    const int S = in_sizes[0] / B;        // x has S*B elements

    const int threads = 64;               // 2 warps/block -> 1 warp per SMSP used
    const int blocks = (B + threads - 1) / threads;
    rnn_scan_kernel<<<blocks, threads>>>(x, h0, W_ih, b_ih, W_hh, b_hh,
                                         fc_W, fc_b, out, S, B);
}